// round 1
// baseline (speedup 1.0000x reference)
#include <cuda_runtime.h>

#define BB     16
#define CC     512
#define SS     1024
#define HEADS  8
#define DH     64
#define INNER  512     // HEADS*DH
#define N3     1536    // 3*INNER
#define ATT_SCALE 0.125f  // 64^-0.5

// Scratch (static device globals — allocation-free per harness rules)
__device__ float g_qkv[(size_t)BB * SS * N3];    // [b][s][h*192 + {q,k,v}]
__device__ float g_res[(size_t)BB * SS * INNER]; // [b][s][h*64+d]

// ---------------------------------------------------------------------------
// Kernel 1: qkv = xs @ W_proj + b_proj, with xs[b][s][c] = x[b][c][s]
// M = B*S = 16384, N = 1536, K = 512. 64x64 tile, 4x4 per thread, Kstep=16.
// ---------------------------------------------------------------------------
__global__ __launch_bounds__(256) void qkv_gemm_k(
    const float* __restrict__ x, const float* __restrict__ Wp,
    const float* __restrict__ bp)
{
    __shared__ float sA[16][68];   // [k][m] (xs^T slab: contiguous in m!)
    __shared__ float sB[16][68];   // [k][n]
    const int n0 = blockIdx.x * 64;
    const int m0 = blockIdx.y * 64;        // m = b*S + s; tiles never cross batch
    const int b  = m0 >> 10;
    const int s0 = m0 & (SS - 1);
    const int tid = threadIdx.x;
    const int tx = tid & 15, ty = tid >> 4;
    const int lk = tid >> 4, lm4 = (tid & 15) << 2;

    float acc[4][4] = {};
    for (int k0 = 0; k0 < CC; k0 += 16) {
        float4 av = *(const float4*)&x[((size_t)(b * CC + k0 + lk)) * SS + s0 + lm4];
        float4 bv = *(const float4*)&Wp[(size_t)(k0 + lk) * N3 + n0 + lm4];
        __syncthreads();
        *(float4*)&sA[lk][lm4] = av;
        *(float4*)&sB[lk][lm4] = bv;
        __syncthreads();
        #pragma unroll
        for (int k = 0; k < 16; k++) {
            float a[4], bq[4];
            #pragma unroll
            for (int r = 0; r < 4; r++) a[r] = sA[k][ty * 4 + r];
            #pragma unroll
            for (int c = 0; c < 4; c++) bq[c] = sB[k][tx * 4 + c];
            #pragma unroll
            for (int r = 0; r < 4; r++)
                #pragma unroll
                for (int c = 0; c < 4; c++)
                    acc[r][c] = fmaf(a[r], bq[c], acc[r][c]);
        }
    }
    const float4 bias = *(const float4*)&bp[n0 + tx * 4];
    #pragma unroll
    for (int r = 0; r < 4; r++) {
        float4 o;
        o.x = acc[r][0] + bias.x; o.y = acc[r][1] + bias.y;
        o.z = acc[r][2] + bias.z; o.w = acc[r][3] + bias.w;
        *(float4*)&g_qkv[((size_t)(m0 + ty * 4 + r)) * N3 + n0 + tx * 4] = o;
    }
}

// ---------------------------------------------------------------------------
// Kernel 2: flash attention per (b,h,q-tile). 64 queries x 64-key tiles,
// d=64, online softmax. 256 threads, 16x16 layout, 4x4 frags.
// ---------------------------------------------------------------------------
__global__ __launch_bounds__(256) void attn_k()
{
    extern __shared__ float sm[];
    float* sQ = sm;                 // 64 x 65
    float* sK = sQ + 64 * 65;
    float* sV = sK + 64 * 65;
    float* sP = sV + 64 * 65;

    const int bh = blockIdx.y;               // 0..127
    const int b = bh >> 3, h = bh & 7;
    const int q0 = blockIdx.x * 64;
    const int tid = threadIdx.x;
    const int tx = tid & 15, ty = tid >> 4;

    const float* qbase = g_qkv + (size_t)b * SS * N3 + h * (3 * DH);

    // Load Q tile (64x64): 1024 float4 / 256 threads = 4 each
    #pragma unroll
    for (int it = 0; it < 4; it++) {
        int idx = tid + it * 256;
        int i = idx >> 4, d4 = (idx & 15) << 2;
        float4 v = *(const float4*)&qbase[(size_t)(q0 + i) * N3 + d4];
        float* p = &sQ[i * 65 + d4];
        p[0] = v.x; p[1] = v.y; p[2] = v.z; p[3] = v.w;
    }

    float m_i[4], l_i[4], o[4][4] = {};
    #pragma unroll
    for (int r = 0; r < 4; r++) { m_i[r] = -1e30f; l_i[r] = 0.f; }
    __syncthreads();

    for (int kt = 0; kt < 16; kt++) {
        const int k0 = kt * 64;
        #pragma unroll
        for (int it = 0; it < 4; it++) {
            int idx = tid + it * 256;
            int j = idx >> 4, d4 = (idx & 15) << 2;
            const float* row = &qbase[(size_t)(k0 + j) * N3];
            float4 kv = *(const float4*)&row[DH + d4];
            float4 vv = *(const float4*)&row[2 * DH + d4];
            float* pk = &sK[j * 65 + d4];
            float* pv = &sV[j * 65 + d4];
            pk[0] = kv.x; pk[1] = kv.y; pk[2] = kv.z; pk[3] = kv.w;
            pv[0] = vv.x; pv[1] = vv.y; pv[2] = vv.z; pv[3] = vv.w;
        }
        __syncthreads();

        // S = Q K^T
        float sf[4][4] = {};
        #pragma unroll 8
        for (int d = 0; d < 64; d++) {
            float a[4], bq[4];
            #pragma unroll
            for (int r = 0; r < 4; r++) a[r] = sQ[(ty * 4 + r) * 65 + d];
            #pragma unroll
            for (int c = 0; c < 4; c++) bq[c] = sK[(tx * 4 + c) * 65 + d];
            #pragma unroll
            for (int r = 0; r < 4; r++)
                #pragma unroll
                for (int c = 0; c < 4; c++)
                    sf[r][c] = fmaf(a[r], bq[c], sf[r][c]);
        }

        // Online softmax per owned row (16-lane butterfly over tx group)
        #pragma unroll
        for (int r = 0; r < 4; r++) {
            float mx = -1e30f;
            #pragma unroll
            for (int c = 0; c < 4; c++) {
                sf[r][c] *= ATT_SCALE;
                mx = fmaxf(mx, sf[r][c]);
            }
            #pragma unroll
            for (int off = 8; off >= 1; off >>= 1)
                mx = fmaxf(mx, __shfl_xor_sync(0xffffffffu, mx, off));
            float m_new = fmaxf(m_i[r], mx);
            float rs = 0.f;
            #pragma unroll
            for (int c = 0; c < 4; c++) {
                float p = __expf(sf[r][c] - m_new);
                rs += p;
                sP[(ty * 4 + r) * 65 + tx * 4 + c] = p;
            }
            #pragma unroll
            for (int off = 8; off >= 1; off >>= 1)
                rs += __shfl_xor_sync(0xffffffffu, rs, off);
            float alpha = __expf(m_i[r] - m_new);
            l_i[r] = l_i[r] * alpha + rs;
            m_i[r] = m_new;
            #pragma unroll
            for (int c = 0; c < 4; c++) o[r][c] *= alpha;
        }
        __syncthreads();

        // O += P V
        #pragma unroll 8
        for (int j = 0; j < 64; j++) {
            float a[4], bq[4];
            #pragma unroll
            for (int r = 0; r < 4; r++) a[r] = sP[(ty * 4 + r) * 65 + j];
            #pragma unroll
            for (int c = 0; c < 4; c++) bq[c] = sV[j * 65 + tx * 4 + c];
            #pragma unroll
            for (int r = 0; r < 4; r++)
                #pragma unroll
                for (int c = 0; c < 4; c++)
                    o[r][c] = fmaf(a[r], bq[c], o[r][c]);
        }
        __syncthreads();
    }

    float* rbase = g_res + ((size_t)b * SS + q0) * INNER + h * DH;
    #pragma unroll
    for (int r = 0; r < 4; r++) {
        float inv = 1.f / l_i[r];
        float4 ov;
        ov.x = o[r][0] * inv; ov.y = o[r][1] * inv;
        ov.z = o[r][2] * inv; ov.w = o[r][3] * inv;
        *(float4*)&rbase[(size_t)(ty * 4 + r) * INNER + tx * 4] = ov;
    }
}

// ---------------------------------------------------------------------------
// Kernel 3: out[b][c][s] = (res[b][s][:] @ W_out[:,c]) + b_out[c] + x[b][c][s]
// Tile: 64c x 64s per block; rows of register tile = c so final writes are
// contiguous in s (coalesced).
// ---------------------------------------------------------------------------
__global__ __launch_bounds__(256) void out_gemm_k(
    const float* __restrict__ x, const float* __restrict__ Wo,
    const float* __restrict__ bo, float* __restrict__ out)
{
    __shared__ float sA[16][68];   // [k][c] from W_out
    __shared__ float sB[16][68];   // [k][s] from res (transposed on store)
    const int s0 = blockIdx.x * 64;
    const int c0 = blockIdx.y * 64;
    const int b  = blockIdx.z;
    const int tid = threadIdx.x;
    const int tx = tid & 15, ty = tid >> 4;
    const int lk = tid >> 4, lc4 = (tid & 15) << 2;
    const int ls = tid >> 2, lk4 = (tid & 3) << 2;

    float acc[4][4] = {};
    for (int k0 = 0; k0 < INNER; k0 += 16) {
        float4 av = *(const float4*)&Wo[(size_t)(k0 + lk) * CC + c0 + lc4];
        float4 bv = *(const float4*)&g_res[((size_t)(b * SS + s0 + ls)) * INNER + k0 + lk4];
        __syncthreads();
        *(float4*)&sA[lk][lc4] = av;
        sB[lk4 + 0][ls] = bv.x; sB[lk4 + 1][ls] = bv.y;
        sB[lk4 + 2][ls] = bv.z; sB[lk4 + 3][ls] = bv.w;
        __syncthreads();
        #pragma unroll
        for (int k = 0; k < 16; k++) {
            float a[4], bq[4];
            #pragma unroll
            for (int r = 0; r < 4; r++) a[r] = sA[k][ty * 4 + r];
            #pragma unroll
            for (int c = 0; c < 4; c++) bq[c] = sB[k][tx * 4 + c];
            #pragma unroll
            for (int r = 0; r < 4; r++)
                #pragma unroll
                for (int c = 0; c < 4; c++)
                    acc[r][c] = fmaf(a[r], bq[c], acc[r][c]);
        }
    }
    #pragma unroll
    for (int r = 0; r < 4; r++) {
        const int c = c0 + ty * 4 + r;
        const float bias = bo[c];
        const size_t base = ((size_t)(b * CC + c)) * SS + s0 + tx * 4;
        float4 xv = *(const float4*)&x[base];
        float4 o;
        o.x = acc[r][0] + bias + xv.x; o.y = acc[r][1] + bias + xv.y;
        o.z = acc[r][2] + bias + xv.z; o.w = acc[r][3] + bias + xv.w;
        *(float4*)&out[base] = o;
    }
}

// ---------------------------------------------------------------------------
extern "C" void kernel_launch(void* const* d_in, const int* in_sizes, int n_in,
                              void* d_out, int out_size)
{
    const float* x  = (const float*)d_in[0];
    const float* Wp = (const float*)d_in[1];
    const float* bp = (const float*)d_in[2];
    const float* Wo = (const float*)d_in[3];
    const float* bo = (const float*)d_in[4];
    float* out = (float*)d_out;

    const int attn_smem = 4 * 64 * 65 * (int)sizeof(float);  // 66560 B
    cudaFuncSetAttribute(attn_k, cudaFuncAttributeMaxDynamicSharedMemorySize,
                         attn_smem);

    dim3 g1(N3 / 64, (BB * SS) / 64);          // 24 x 256
    qkv_gemm_k<<<g1, 256>>>(x, Wp, bp);

    dim3 g2(SS / 64, BB * HEADS);              // 16 x 128
    attn_k<<<g2, 256, attn_smem>>>();

    dim3 g3(SS / 64, CC / 64, BB);             // 16 x 8 x 16
    out_gemm_k<<<g3, 256>>>(x, Wo, bo, out);
}

// round 3
// speedup vs baseline: 1.2077x; 1.2077x over previous
#include <cuda_runtime.h>

#define BB     16
#define CC     512
#define SS     1024
#define HEADS  8
#define DH     64
#define INNER  512     // HEADS*DH
#define N3     1536    // 3*INNER
#define ATT_SCALE 0.125f  // 64^-0.5

// Scratch (static device globals — allocation-free per harness rules)
__device__ float g_qkv[(size_t)BB * SS * N3];    // [b][s][h*192 + {q,k,v}]
__device__ float g_res[(size_t)BB * SS * INNER]; // [b][s][h*64+d]

// ---------------------------------------------------------------------------
// Kernel 1: qkv = xs @ W_proj + b_proj, with xs[b][s][c] = x[b][c][s]
// M = B*S = 16384, N = 1536, K = 512. 128x128 tile, 8x8 per thread, Kstep=16.
// ---------------------------------------------------------------------------
__global__ __launch_bounds__(256, 2) void qkv_gemm_k(
    const float* __restrict__ x, const float* __restrict__ Wp,
    const float* __restrict__ bp)
{
    __shared__ float sA[16][132];   // [k][m] (xs^T slab: contiguous in m)
    __shared__ float sB[16][132];   // [k][n]
    const int n0 = blockIdx.x * 128;
    const int m0 = blockIdx.y * 128;       // m = b*S + s; tiles never cross batch
    const int b  = m0 >> 10;
    const int s0 = m0 & (SS - 1);
    const int tid = threadIdx.x;
    const int tx = tid & 15, ty = tid >> 4;
    const int lk = tid >> 4, lm4 = (tid & 15) << 2;

    float acc[8][8] = {};
    for (int k0 = 0; k0 < CC; k0 += 16) {
        const size_t arow = ((size_t)(b * CC + k0 + lk)) * SS + s0 + lm4;
        const size_t brow = (size_t)(k0 + lk) * N3 + n0 + lm4;
        float4 av0 = *(const float4*)&x[arow];
        float4 av1 = *(const float4*)&x[arow + 64];
        float4 bv0 = *(const float4*)&Wp[brow];
        float4 bv1 = *(const float4*)&Wp[brow + 64];
        __syncthreads();
        *(float4*)&sA[lk][lm4]      = av0;
        *(float4*)&sA[lk][lm4 + 64] = av1;
        *(float4*)&sB[lk][lm4]      = bv0;
        *(float4*)&sB[lk][lm4 + 64] = bv1;
        __syncthreads();
        #pragma unroll
        for (int k = 0; k < 16; k++) {
            float a[8], bq[8];
            #pragma unroll
            for (int r = 0; r < 4; r++) {
                a[r]     = sA[k][ty * 4 + r];
                a[r + 4] = sA[k][64 + ty * 4 + r];
                bq[r]     = sB[k][tx * 4 + r];
                bq[r + 4] = sB[k][64 + tx * 4 + r];
            }
            #pragma unroll
            for (int r = 0; r < 8; r++)
                #pragma unroll
                for (int c = 0; c < 8; c++)
                    acc[r][c] = fmaf(a[r], bq[c], acc[r][c]);
        }
    }
    const float4 bias0 = *(const float4*)&bp[n0 + tx * 4];
    const float4 bias1 = *(const float4*)&bp[n0 + 64 + tx * 4];
    #pragma unroll
    for (int r = 0; r < 8; r++) {
        const int row = m0 + ((r < 4) ? (ty * 4 + r) : (64 + ty * 4 + r - 4));
        float* dst = &g_qkv[(size_t)row * N3 + n0 + tx * 4];
        float4 o0, o1;
        o0.x = acc[r][0] + bias0.x; o0.y = acc[r][1] + bias0.y;
        o0.z = acc[r][2] + bias0.z; o0.w = acc[r][3] + bias0.w;
        o1.x = acc[r][4] + bias1.x; o1.y = acc[r][5] + bias1.y;
        o1.z = acc[r][6] + bias1.z; o1.w = acc[r][7] + bias1.w;
        *(float4*)dst = o0;
        *(float4*)(dst + 64) = o1;
    }
}

// ---------------------------------------------------------------------------
// Kernel 2: flash attention per (b,h,q-tile). 128 queries x 64-key tiles,
// d=64, online softmax. 256 threads, 16x16 layout, 8x4 frags.
// ---------------------------------------------------------------------------
__global__ __launch_bounds__(256, 2) void attn_k()
{
    extern __shared__ float sm[];
    float* sQ = sm;                 // 128 x 65
    float* sK = sQ + 128 * 65;      // 64 x 65
    float* sV = sK + 64 * 65;       // 64 x 65
    float* sP = sV + 64 * 65;       // 128 x 65

    const int bh = blockIdx.y;               // 0..127
    const int b = bh >> 3, h = bh & 7;
    const int q0 = blockIdx.x * 128;
    const int tid = threadIdx.x;
    const int tx = tid & 15, ty = tid >> 4;

    const float* qbase = g_qkv + (size_t)b * SS * N3 + h * (3 * DH);

    // Load Q tile (128x64): 2048 float4 / 256 threads = 8 each
    #pragma unroll
    for (int it = 0; it < 8; it++) {
        int idx = tid + it * 256;
        int i = idx >> 4, d4 = (idx & 15) << 2;
        float4 v = *(const float4*)&qbase[(size_t)(q0 + i) * N3 + d4];
        float* p = &sQ[i * 65 + d4];
        p[0] = v.x; p[1] = v.y; p[2] = v.z; p[3] = v.w;
    }

    float m_i[8], l_i[8], o[8][4] = {};
    #pragma unroll
    for (int r = 0; r < 8; r++) { m_i[r] = -1e30f; l_i[r] = 0.f; }

    for (int kt = 0; kt < 16; kt++) {
        const int k0 = kt * 64;
        // Barrier: Q-load (first iter) / previous PV reads of sK,sV done.
        __syncthreads();
        // Load K,V tiles (64x64 each = 1024 float4 each): 4 iters x 256 thr.
        #pragma unroll
        for (int it = 0; it < 4; it++) {
            int idx = tid + it * 256;
            int j = idx >> 4, d4 = (idx & 15) << 2;
            const float* row = &qbase[(size_t)(k0 + j) * N3];
            float4 kv = *(const float4*)&row[DH + d4];
            float4 vv = *(const float4*)&row[2 * DH + d4];
            float* pk = &sK[j * 65 + d4];
            float* pv = &sV[j * 65 + d4];
            pk[0] = kv.x; pk[1] = kv.y; pk[2] = kv.z; pk[3] = kv.w;
            pv[0] = vv.x; pv[1] = vv.y; pv[2] = vv.z; pv[3] = vv.w;
        }
        __syncthreads();

        // S = Q K^T  (8 q-rows x 4 k-cols per thread)
        float sf[8][4] = {};
        #pragma unroll 8
        for (int d = 0; d < 64; d++) {
            float a[8], bq[4];
            #pragma unroll
            for (int r = 0; r < 4; r++) {
                a[r]     = sQ[(ty * 4 + r) * 65 + d];
                a[r + 4] = sQ[(64 + ty * 4 + r) * 65 + d];
            }
            #pragma unroll
            for (int c = 0; c < 4; c++) bq[c] = sK[(tx * 4 + c) * 65 + d];
            #pragma unroll
            for (int r = 0; r < 8; r++)
                #pragma unroll
                for (int c = 0; c < 4; c++)
                    sf[r][c] = fmaf(a[r], bq[c], sf[r][c]);
        }

        // Online softmax per owned row (16-lane butterfly over tx group)
        #pragma unroll
        for (int r = 0; r < 8; r++) {
            const int qrow = (r < 4) ? (ty * 4 + r) : (64 + ty * 4 + r - 4);
            float mx = -1e30f;
            #pragma unroll
            for (int c = 0; c < 4; c++) {
                sf[r][c] *= ATT_SCALE;
                mx = fmaxf(mx, sf[r][c]);
            }
            #pragma unroll
            for (int off = 8; off >= 1; off >>= 1)
                mx = fmaxf(mx, __shfl_xor_sync(0xffffffffu, mx, off));
            float m_new = fmaxf(m_i[r], mx);
            float rs = 0.f;
            #pragma unroll
            for (int c = 0; c < 4; c++) {
                float p = __expf(sf[r][c] - m_new);
                rs += p;
                sP[qrow * 65 + tx * 4 + c] = p;
            }
            #pragma unroll
            for (int off = 8; off >= 1; off >>= 1)
                rs += __shfl_xor_sync(0xffffffffu, rs, off);
            float alpha = __expf(m_i[r] - m_new);
            l_i[r] = l_i[r] * alpha + rs;
            m_i[r] = m_new;
            #pragma unroll
            for (int c = 0; c < 4; c++) o[r][c] *= alpha;
        }
        __syncwarp();   // sP rows produced/consumed within the same warp

        // O += P V
        #pragma unroll 8
        for (int j = 0; j < 64; j++) {
            float a[8], bq[4];
            #pragma unroll
            for (int r = 0; r < 4; r++) {
                a[r]     = sP[(ty * 4 + r) * 65 + j];
                a[r + 4] = sP[(64 + ty * 4 + r) * 65 + j];
            }
            #pragma unroll
            for (int c = 0; c < 4; c++) bq[c] = sV[j * 65 + tx * 4 + c];
            #pragma unroll
            for (int r = 0; r < 8; r++)
                #pragma unroll
                for (int c = 0; c < 4; c++)
                    o[r][c] = fmaf(a[r], bq[c], o[r][c]);
        }
    }

    float* rbase = g_res + ((size_t)b * SS + q0) * INNER + h * DH;
    #pragma unroll
    for (int r = 0; r < 8; r++) {
        const int qrow = (r < 4) ? (ty * 4 + r) : (64 + ty * 4 + r - 4);
        float inv = 1.f / l_i[r];
        float4 ov;
        ov.x = o[r][0] * inv; ov.y = o[r][1] * inv;
        ov.z = o[r][2] * inv; ov.w = o[r][3] * inv;
        *(float4*)&rbase[(size_t)qrow * INNER + tx * 4] = ov;
    }
}

// ---------------------------------------------------------------------------
// Kernel 3: out[b][c][s] = (res[b][s][:] @ W_out[:,c]) + b_out[c] + x[b][c][s]
// 128c x 128s tile, 8x8 per thread. Register rows = c so writes are
// contiguous float4 in s (coalesced).
// ---------------------------------------------------------------------------
__global__ __launch_bounds__(256, 2) void out_gemm_k(
    const float* __restrict__ x, const float* __restrict__ Wo,
    const float* __restrict__ bo, float* __restrict__ out)
{
    __shared__ float sA[16][132];   // [k][c] from W_out
    __shared__ float sB[16][132];   // [k][s] from res (transposed on store)
    const int s0 = blockIdx.x * 128;
    const int c0 = blockIdx.y * 128;
    const int b  = blockIdx.z;
    const int tid = threadIdx.x;
    const int tx = tid & 15, ty = tid >> 4;
    const int lk = tid >> 4, lc4 = (tid & 15) << 2;
    const int ls = tid >> 1, lkb = (tid & 1) << 3;

    float acc[8][8] = {};
    for (int k0 = 0; k0 < INNER; k0 += 16) {
        const size_t arow = (size_t)(k0 + lk) * CC + c0 + lc4;
        float4 av0 = *(const float4*)&Wo[arow];
        float4 av1 = *(const float4*)&Wo[arow + 64];
        const size_t brow = ((size_t)(b * SS + s0 + ls)) * INNER + k0 + lkb;
        float4 bv0 = *(const float4*)&g_res[brow];
        float4 bv1 = *(const float4*)&g_res[brow + 4];
        __syncthreads();
        *(float4*)&sA[lk][lc4]      = av0;
        *(float4*)&sA[lk][lc4 + 64] = av1;
        sB[lkb + 0][ls] = bv0.x; sB[lkb + 1][ls] = bv0.y;
        sB[lkb + 2][ls] = bv0.z; sB[lkb + 3][ls] = bv0.w;
        sB[lkb + 4][ls] = bv1.x; sB[lkb + 5][ls] = bv1.y;
        sB[lkb + 6][ls] = bv1.z; sB[lkb + 7][ls] = bv1.w;
        __syncthreads();
        #pragma unroll
        for (int k = 0; k < 16; k++) {
            float a[8], bq[8];
            #pragma unroll
            for (int r = 0; r < 4; r++) {
                a[r]     = sA[k][ty * 4 + r];
                a[r + 4] = sA[k][64 + ty * 4 + r];
                bq[r]     = sB[k][tx * 4 + r];
                bq[r + 4] = sB[k][64 + tx * 4 + r];
            }
            #pragma unroll
            for (int r = 0; r < 8; r++)
                #pragma unroll
                for (int c = 0; c < 8; c++)
                    acc[r][c] = fmaf(a[r], bq[c], acc[r][c]);
        }
    }
    #pragma unroll
    for (int r = 0; r < 8; r++) {
        const int c = c0 + ((r < 4) ? (ty * 4 + r) : (64 + ty * 4 + r - 4));
        const float bias = bo[c];
        const size_t base = ((size_t)(b * CC + c)) * SS + s0 + tx * 4;
        float4 xv0 = *(const float4*)&x[base];
        float4 xv1 = *(const float4*)&x[base + 64];
        float4 o0, o1;
        o0.x = acc[r][0] + bias + xv0.x; o0.y = acc[r][1] + bias + xv0.y;
        o0.z = acc[r][2] + bias + xv0.z; o0.w = acc[r][3] + bias + xv0.w;
        o1.x = acc[r][4] + bias + xv1.x; o1.y = acc[r][5] + bias + xv1.y;
        o1.z = acc[r][6] + bias + xv1.z; o1.w = acc[r][7] + bias + xv1.w;
        *(float4*)&out[base] = o0;
        *(float4*)&out[base + 64] = o1;
    }
}

// ---------------------------------------------------------------------------
extern "C" void kernel_launch(void* const* d_in, const int* in_sizes, int n_in,
                              void* d_out, int out_size)
{
    const float* x  = (const float*)d_in[0];
    const float* Wp = (const float*)d_in[1];
    const float* bp = (const float*)d_in[2];
    const float* Wo = (const float*)d_in[3];
    const float* bo = (const float*)d_in[4];
    float* out = (float*)d_out;

    const int attn_smem = (128 + 64 + 64 + 128) * 65 * (int)sizeof(float); // 99840 B
    cudaFuncSetAttribute(attn_k, cudaFuncAttributeMaxDynamicSharedMemorySize,
                         attn_smem);

    dim3 g1(N3 / 128, (BB * SS) / 128);        // 12 x 128
    qkv_gemm_k<<<g1, 256>>>(x, Wp, bp);

    dim3 g2(SS / 128, BB * HEADS);             // 8 x 128
    attn_k<<<g2, 256, attn_smem>>>();

    dim3 g3(SS / 128, CC / 128, BB);           // 8 x 4 x 16
    out_gemm_k<<<g3, 256>>>(x, Wo, bo, out);
}